// round 13
// baseline (speedup 1.0000x reference)
#include <cuda_runtime.h>
#include <cstddef>

// ---------------------------------------------------------------------------
// RBFolution: out[b,oh,ow,f] = exp(-beta[f] * (||p||^2 - 2 p.ccs[:,f] + ||c_f||^2))
// B=32,H=W=112,C=32,F=128,D=288, valid 3x3 -> Ho=Wo=110.
//
// R13: packed-FFMA2 mainloop. Evidence: two different kernels both pinned at
// fma=~50% / issue=~57% -> FFMA-3reg rt_SMSP=2 ceiling (RF banking). Escape:
// PTX fma.rn.f32x2 = 2 FMAs per issue slot, same fp32 rounding.
//
// Block: 256 threads, tile 16x8 pixels x 64 filters (F-split, 2 blocks/SM).
//   fid  = tid & 3        -> filters g*16 + fid*4 .. +3, g = 0..3
//   prow = (tid>>2) & 15  -> pixel row in tile
//   pcg  = tid >> 6       -> pixel column pair (2 cols each)
// Per thread: 2 px x 16 filters = 16 packed f32x2 accumulators.
// ---------------------------------------------------------------------------

#define Bn 32
#define Hn 112
#define Wn 112
#define Cn 32
#define Fn 128
#define FHALF 64
#define HoN 110
#define WoN 110
#define Dn 288            // 3*3*Cn

#define TILE_H 16
#define TILE_W 8
#define THREADS 256

#define XS_H (TILE_H + 2)         // 18
#define XS_W (TILE_W + 2)         // 10
#define XS_RPITCH (XS_W * Cn + 4) // 324 floats: row stride = 16B mod 128B -> A conflict-free

#define SMEM_FLOATS (Dn * FHALF + XS_H * XS_RPITCH + TILE_H * TILE_W + FHALF + FHALF)
#define SMEM_BYTES (SMEM_FLOATS * 4)

// packed f32x2 FMA: d = a*b + d elementwise on {lo,hi}
#define FMA2(d, a, b) \
    asm("fma.rn.f32x2 %0, %1, %2, %0;" : "+l"(d) : "l"(a), "l"(b))
// splat one fp32 into both lanes of an f32x2
#define SPLAT2(d, s) \
    asm("mov.b64 %0, {%1, %1};" : "=l"(d) : "f"(s))
// unpack f32x2 -> two fp32
#define UNPACK2(lo, hi, s) \
    asm("mov.b64 {%0, %1}, %2;" : "=f"(lo), "=f"(hi) : "l"(s))

__global__ void __launch_bounds__(THREADS, 2)
rbfolution_kernel(const float* __restrict__ x,
                  const float* __restrict__ ccs,
                  const float* __restrict__ beta,
                  float* __restrict__ out)
{
    extern __shared__ float smem[];
    float* sccs  = smem;                         // [Dn][FHALF]   73728 B
    float* xs    = sccs + Dn * FHALF;            // [XS_H][XS_RPITCH]  23328 B
    float* psq   = xs + XS_H * XS_RPITCH;        // [128] per-pixel ||p||^2
    float* csq   = psq + TILE_H * TILE_W;        // [64] per-filter ||c||^2
    float* sbeta = csq + FHALF;                  // [64]

    const int tid = threadIdx.x;
    const int bz  = blockIdx.z;
    const int b   = bz >> 1;
    const int fh  = bz & 1;                      // filter half: 0 or 1
    const int oh0 = blockIdx.y * TILE_H;
    const int ow0 = blockIdx.x * TILE_W;

    // ---- load this block's 64-filter slice of ccs into smem ----
    {
        const float4* src = reinterpret_cast<const float4*>(ccs);
        float4* dst = reinterpret_cast<float4*>(sccs);
        const int fh16 = fh * (FHALF / 4);
        #pragma unroll
        for (int it = 0; it < (Dn * FHALF / 4) / THREADS; ++it) {  // 18 iters
            int i = tid + it * THREADS;
            int d = i >> 4;
            int v = i & 15;
            dst[i] = src[d * (Fn / 4) + fh16 + v];
        }
    }

    // ---- load x halo tile (18 x 10 x 32), zero-fill out-of-bounds ----
    {
        const int NV = XS_H * XS_W * (Cn / 4);   // 1440 float4 slots (logical)
        for (int i = tid; i < NV; i += THREADS) {
            int pos = i / (Cn / 4);
            int v   = i % (Cn / 4);
            int r   = pos / XS_W;
            int col = pos % XS_W;
            int gr  = oh0 + r;
            int gc  = ow0 + col;
            float4 val = make_float4(0.f, 0.f, 0.f, 0.f);
            if (gr < Hn && gc < Wn) {
                val = *reinterpret_cast<const float4*>(
                    x + (((size_t)b * Hn + gr) * Wn + gc) * Cn + v * 4);
            }
            float* d = xs + r * XS_RPITCH + col * Cn + v * 4;
            d[0] = val.x; d[1] = val.y; d[2] = val.z; d[3] = val.w;
        }
    }
    __syncthreads();

    // ---- threads 0-127: per-pixel ||p||^2 ; threads 128-191: ||c||^2 + beta ----
    if (tid < TILE_H * TILE_W) {
        const int ty = tid >> 3;
        const int tx = tid & 7;
        float s = 0.f;
        #pragma unroll
        for (int tr = 0; tr < 3; ++tr) {
            #pragma unroll
            for (int tc = 0; tc < 3; ++tc) {
                const float* p = xs + (ty + tr) * XS_RPITCH + (tx + tc) * Cn;
                #pragma unroll
                for (int c = 0; c < Cn; ++c) {
                    float v = p[c];
                    s = fmaf(v, v, s);
                }
            }
        }
        psq[tid] = s;
    } else if (tid < 128 + FHALF) {
        const int f = tid - 128;
        float s = 0.f;
        #pragma unroll 8
        for (int d = 0; d < Dn; ++d) {
            float v = sccs[d * FHALF + f];
            s = fmaf(v, v, s);
        }
        csq[f] = s;
        sbeta[f] = beta[fh * FHALF + f];
    }
    __syncthreads();

    // ---- main loop: packed acc[px][pair] over 2 px x 16 filters ----
    const int fid  = tid & 3;          // 4 filter groups; thread owns g*16+fid*4..+3
    const int prow = (tid >> 2) & 15;  // pixel row within tile
    const int pcg  = tid >> 6;         // pixel column pair (0..3)

    unsigned long long acc[2][8];      // [px][pair]: pair p of group g at index g*2+(p&1)
    #pragma unroll
    for (int i = 0; i < 2; ++i)
        #pragma unroll
        for (int j = 0; j < 8; ++j)
            acc[i][j] = 0ULL;

    #pragma unroll 1
    for (int tr = 0; tr < 3; ++tr) {
        #pragma unroll 1
        for (int tc = 0; tc < 3; ++tc) {
            const float* ap = xs + (prow + tr) * XS_RPITCH + (pcg * 2 + tc) * Cn;
            const float* bp = sccs + (size_t)(tr * 3 + tc) * Cn * FHALF + fid * 4;
            #pragma unroll 2
            for (int c4 = 0; c4 < Cn / 4; ++c4) {
                float a0[4], a1[4];
                *reinterpret_cast<float4*>(a0) =
                    *reinterpret_cast<const float4*>(ap + c4 * 4);
                *reinterpret_cast<float4*>(a1) =
                    *reinterpret_cast<const float4*>(ap + Cn + c4 * 4);
                #pragma unroll
                for (int cc = 0; cc < 4; ++cc) {
                    unsigned long long pa0, pa1;
                    SPLAT2(pa0, a0[cc]);
                    SPLAT2(pa1, a1[cc]);
                    const float* brow = bp + (c4 * 4 + cc) * FHALF;
                    #pragma unroll
                    for (int g = 0; g < 4; ++g) {
                        // 16B load -> two f32x2 pairs (filters g*16+fid*4 .. +3)
                        const ulonglong2 bv =
                            *reinterpret_cast<const ulonglong2*>(brow + g * 16);
                        FMA2(acc[0][g * 2 + 0], pa0, bv.x);
                        FMA2(acc[0][g * 2 + 1], pa0, bv.y);
                        FMA2(acc[1][g * 2 + 0], pa1, bv.x);
                        FMA2(acc[1][g * 2 + 1], pa1, bv.y);
                    }
                }
            }
        }
    }

    // ---- epilogue: score = psq + csq - 2*dot ; out = exp(-beta*score) ----
    const int oh = oh0 + prow;
    if (oh < HoN) {
        #pragma unroll
        for (int px = 0; px < 2; ++px) {
            const int ow = ow0 + pcg * 2 + px;
            if (ow < WoN) {
                const float ps = psq[prow * TILE_W + pcg * 2 + px];
                float* op = out + (((size_t)b * HoN + oh) * WoN + ow) * Fn
                                + fh * FHALF;
                #pragma unroll
                for (int g = 0; g < 4; ++g) {
                    const int f0 = g * 16 + fid * 4;
                    float d0, d1, d2, d3;
                    UNPACK2(d0, d1, acc[px][g * 2 + 0]);
                    UNPACK2(d2, d3, acc[px][g * 2 + 1]);
                    float4 r;
                    r.x = __expf(-sbeta[f0 + 0] * (ps + csq[f0 + 0] - 2.f * d0));
                    r.y = __expf(-sbeta[f0 + 1] * (ps + csq[f0 + 1] - 2.f * d1));
                    r.z = __expf(-sbeta[f0 + 2] * (ps + csq[f0 + 2] - 2.f * d2));
                    r.w = __expf(-sbeta[f0 + 3] * (ps + csq[f0 + 3] - 2.f * d3));
                    *reinterpret_cast<float4*>(op + f0) = r;
                }
            }
        }
    }
}

extern "C" void kernel_launch(void* const* d_in, const int* in_sizes, int n_in,
                              void* d_out, int out_size)
{
    (void)in_sizes; (void)n_in; (void)out_size;
    const float* x    = (const float*)d_in[0];
    const float* ccs  = (const float*)d_in[1];
    const float* beta = (const float*)d_in[2];
    float* out = (float*)d_out;

    cudaFuncSetAttribute(rbfolution_kernel,
                         cudaFuncAttributeMaxDynamicSharedMemorySize, SMEM_BYTES);

    dim3 grid((WoN + TILE_W - 1) / TILE_W,   // 14
              (HoN + TILE_H - 1) / TILE_H,   // 7
              Bn * 2);                       // 32 batches x 2 filter halves
    rbfolution_kernel<<<grid, THREADS, SMEM_BYTES>>>(x, ccs, beta, out);
}